// round 13
// baseline (speedup 1.0000x reference)
#include <cuda_runtime.h>
#include <math.h>

#define VSZ 30000
#define DM  640
#define NL  6
#define NH  8
#define DHD 80
#define FFH 2560
#define BB  4
#define SSQ 33
#define EOS_TOK 2
#define NBLK 64
#define NTHR 1024
#define NWP  32            // warps per block
#define TOTW (NBLK*NWP)    // 2048 global warps

struct Params {
    const int* words;
    const float *emb,*Wq,*bq,*Wk,*bk,*Wv,*bv,*Wo,*bo;
    const float *ln1s,*ln1b,*W1,*b1,*W2,*b2,*ln2s,*ln2b,*lmW,*lmb;
    float* out;
};

// ------------------------- device state -------------------------
__device__ unsigned g_bar_count;
__device__ unsigned g_bar_gen;
__device__ int g_stop;
__device__ int g_inp[BB*SSQ];
__device__ unsigned long long g_best[BB];
__device__ float g_h [36*DM];
__device__ float g_h2[36*DM];
__device__ float g_q [36*DM];
__device__ float g_ao[36*DM];
__device__ float g_r1[36*DM];
__device__ float g_f1[36*FFH];
__device__ float g_r2[36*DM];
__device__ float g_kc[NL*BB*SSQ*DM];
__device__ float g_vc[NL*BB*SSQ*DM];

struct Shr {
    const float* rpE[36];
    const float* rpH[36];
    const float* rpH2[36];
    const float* rpAO[36];
    const float* rpF1[36];
    const float* rpLM[4];
    unsigned long long sk[NWP*4];
};

// ------------------------- grid barrier -------------------------
__device__ __forceinline__ void gsync(unsigned &gen) {
    __syncthreads();
    if (threadIdx.x == 0) {
        __threadfence();                       // release
        unsigned arrived = atomicAdd(&g_bar_count, 1u);
        if (arrived == NBLK - 1u) {
            g_bar_count = 0u;
            __threadfence();
            atomicAdd(&g_bar_gen, 1u);
        } else {
            while (atomicAdd(&g_bar_gen, 0u) == gen) __nanosleep(32);
        }
        __threadfence();                       // acquire
    }
    gen++;
    __syncthreads();
}

// ------------------------- warp dot4: acc[TM][4] = rows x W[:, n4..n4+3] ----------
// lanes split K into 32 slices; after butterfly all lanes hold the 4*TM totals.
template<int TM>
__device__ __forceinline__ void warp_dot4(const float* const* rowp, int row0,
                                          const float* __restrict__ W, int ldw,
                                          int n4, int K, float acc[TM][4]) {
    const int lane = threadIdx.x & 31;
    const int KL = K >> 5;
    const int k0 = lane * KL;
#pragma unroll
    for (int m = 0; m < TM; m++) { acc[m][0]=0.f; acc[m][1]=0.f; acc[m][2]=0.f; acc[m][3]=0.f; }
    const float* a0[TM];
#pragma unroll
    for (int m = 0; m < TM; m++) a0[m] = rowp[row0 + m] + k0;
    const char* Wb = (const char*)(W + (long long)k0 * ldw + n4);
    const long long step = (long long)ldw * sizeof(float);
#pragma unroll 4
    for (int kk = 0; kk < KL; kk++) {
        float4 w = __ldg((const float4*)(Wb + (long long)kk * step));
#pragma unroll
        for (int m = 0; m < TM; m++) {
            float a = a0[m][kk];
            acc[m][0] = fmaf(a, w.x, acc[m][0]);
            acc[m][1] = fmaf(a, w.y, acc[m][1]);
            acc[m][2] = fmaf(a, w.z, acc[m][2]);
            acc[m][3] = fmaf(a, w.w, acc[m][3]);
        }
    }
#pragma unroll
    for (int off = 16; off > 0; off >>= 1)
#pragma unroll
        for (int m = 0; m < TM; m++)
#pragma unroll
            for (int j = 0; j < 4; j++)
                acc[m][j] += __shfl_xor_sync(0xffffffffu, acc[m][j], off);
}

// ------------------------- QKV phase -------------------------
template<int NC>
__device__ void qkv_phase(const Params& P, int l, int p0, const float* const* rowp) {
    constexpr int M = 4*NC;
    const int gw = blockIdx.x*NWP + (threadIdx.x >> 5);
    const int lane = threadIdx.x & 31;
    const int GPM = DM/4;                  // 160 groups per matrix
    for (int g = gw; g < 3*GPM; g += TOTW) {
        int sel = g / GPM;
        int n4 = (g - sel*GPM) * 4;
        const float* W    = ((sel==0) ? P.Wq : (sel==1) ? P.Wk : P.Wv) + (long long)l*DM*DM;
        const float* bias = ((sel==0) ? P.bq : (sel==1) ? P.bk : P.bv) + l*DM;
        for (int t0 = 0; t0 < M; t0 += 4) {
            float acc[4][4];
            warp_dot4<4>(rowp, t0, W, DM, n4, DM, acc);
            if (lane < 16) {
                int mi = lane >> 2, j = lane & 3;
                int m = t0 + mi;
                float v = acc[mi][j] + __ldg(bias + n4 + j);
                int b = m / NC, jj = m - b*NC, p = p0 + jj;
                if (sel == 0)      g_q[m*DM + n4 + j] = v;
                else if (sel == 1) g_kc[((l*BB + b)*SSQ + p)*DM + n4 + j] = v;
                else               g_vc[((l*BB + b)*SSQ + p)*DM + n4 + j] = v;
            }
        }
    }
}

// ------------------------- generic GEMM phase -------------------------
template<int M, bool RELU>
__device__ void gemm_phase(const float* const* rowp, const float* __restrict__ W,
                           const float* __restrict__ bias, float* out, int K, int N) {
    const int gw = blockIdx.x*NWP + (threadIdx.x >> 5);
    const int lane = threadIdx.x & 31;
    const int NG = N >> 2;
    for (int g = gw; g < NG; g += TOTW) {
        int n4 = g << 2;
        for (int t0 = 0; t0 < M; t0 += 4) {
            float acc[4][4];
            warp_dot4<4>(rowp, t0, W, N, n4, K, acc);
            if (lane < 16) {
                int mi = lane >> 2, j = lane & 3;
                float v = acc[mi][j] + __ldg(bias + n4 + j);
                if (RELU) v = fmaxf(v, 0.f);
                out[(t0 + mi)*N + n4 + j] = v;
            }
        }
    }
}

// ------------------------- attention phase -------------------------
template<int NC>
__device__ void attn_phase(int l, int p0) {
    const int wp = threadIdx.x >> 5, lane = threadIdx.x & 31;
    const int total = BB*NH*NC;
    for (int tup = blockIdx.x*NWP + wp; tup < total; tup += TOTW) {
        int b = tup / (NH*NC);
        int rem = tup - b*NH*NC;
        int h = rem / NC, j = rem - h*NC;
        int p = p0 + j, nk = p + 1;
        int r = b*NC + j;
        float* qp = g_q + r*DM + h*DHD;
        float sc = -1e30f;
        if (lane < nk) {
            float* kp = g_kc + ((l*BB + b)*SSQ + lane)*DM + h*DHD;
            float sv = 0.f;
#pragma unroll
            for (int d = 0; d < DHD; d++) sv = fmaf(qp[d], kp[d], sv);
            sc = sv / sqrtf((float)DHD);
        }
        float mx = sc;
        for (int o = 16; o > 0; o >>= 1) mx = fmaxf(mx, __shfl_xor_sync(0xffffffffu, mx, o));
        float e = (lane < nk) ? expf(sc - mx) : 0.f;
        float sum = e;
        for (int o = 16; o > 0; o >>= 1) sum += __shfl_xor_sync(0xffffffffu, sum, o);
        float o0 = 0.f, o1 = 0.f, o2 = 0.f;
        float* vb = g_vc + ((l*BB + b)*SSQ)*DM + h*DHD;
        for (int jk = 0; jk < nk; jk++) {
            float pj = __shfl_sync(0xffffffffu, e, jk) / sum;
            float* vp = vb + jk*DM;
            o0 = fmaf(pj, vp[lane],      o0);
            o1 = fmaf(pj, vp[lane + 32], o1);
            if (lane < 16) o2 = fmaf(pj, vp[lane + 64], o2);
        }
        float* ao = g_ao + r*DM + h*DHD;
        ao[lane] = o0; ao[lane + 32] = o1;
        if (lane < 16) ao[lane + 64] = o2;
    }
}

// ------------------------- warp LayerNorm (DM=640=32*20) -------------------------
__device__ __forceinline__ void ln_row_warp(const float* a, const float* r,
                                            const float* __restrict__ sc,
                                            const float* __restrict__ bi,
                                            float* dst) {
    int lane = threadIdx.x & 31;
    float v[20];
    float sum = 0.f;
#pragma unroll
    for (int i = 0; i < 20; i++) {
        float x = a[lane + 32*i] + r[lane + 32*i];
        v[i] = x; sum += x;
    }
#pragma unroll
    for (int o = 16; o > 0; o >>= 1) sum += __shfl_xor_sync(0xffffffffu, sum, o);
    float mean = sum / DM;
    float vs = 0.f;
#pragma unroll
    for (int i = 0; i < 20; i++) { float d = v[i] - mean; vs += d*d; }
#pragma unroll
    for (int o = 16; o > 0; o >>= 1) vs += __shfl_xor_sync(0xffffffffu, vs, o);
    float dn = sqrtf(vs / DM + 1e-6f);
#pragma unroll
    for (int i = 0; i < 20; i++)
        dst[lane + 32*i] = (v[i] - mean) / dn * __ldg(sc + lane + 32*i)
                           + __ldg(bi + lane + 32*i);
}

template<int M>
__device__ void ln_phase(const float* a, const float* r,
                         const float* __restrict__ sc, const float* __restrict__ bi,
                         float* dst) {
    int gw = blockIdx.x*NWP + (threadIdx.x >> 5);
    for (int row = gw; row < M; row += TOTW)
        ln_row_warp(a + row*DM, r + row*DM, sc, bi, dst + row*DM);
}

// ------------------------- LM head + argmax phase -------------------------
__device__ void lm_phase(const Params& P, const float* const* rowp,
                         unsigned long long* sk) {
    const int wp = threadIdx.x >> 5, lane = threadIdx.x & 31;
    const int gw = blockIdx.x*NWP + wp;
    unsigned long long rb = 0ull;
    for (int g = gw; g < VSZ/4; g += TOTW) {
        int n4 = g << 2;
        float acc[4][4];
        warp_dot4<4>(rowp, 0, P.lmW, VSZ, n4, DM, acc);
        unsigned long long key = 0ull;
        if (lane < 16) {
            int b = lane >> 2, j = lane & 3;
            float v = acc[b][j] + __ldg(P.lmb + n4 + j);
            unsigned u = __float_as_uint(v);
            u = (u & 0x80000000u) ? ~u : (u | 0x80000000u);
            key = ((unsigned long long)u << 32) | (unsigned)(0xFFFFFFFFu - (unsigned)(n4 + j));
        }
        unsigned long long o1 = __shfl_xor_sync(0xffffffffu, key, 1); if (o1 > key) key = o1;
        unsigned long long o2 = __shfl_xor_sync(0xffffffffu, key, 2); if (o2 > key) key = o2;
        if (key > rb) rb = key;
    }
    if (lane < 16 && (lane & 3) == 0) sk[wp*4 + (lane >> 2)] = rb;
    else if (lane == 16) { /* nothing */ }
    __syncthreads();
    if (wp == 0) {
        for (int b = 0; b < 4; b++) {
            unsigned long long v = sk[lane*4 + b];
            for (int off = 16; off > 0; off >>= 1) {
                unsigned long long u = __shfl_xor_sync(0xffffffffu, v, off);
                if (u > v) v = u;
            }
            if (lane == 0 && v) atomicMax(&g_best[b], v);
        }
    }
}

// ------------------------- one generation step -------------------------
template<int NC>
__device__ void do_step(int p0, int cl, const Params& P, unsigned &gen, Shr& S) {
    constexpr int M = 4*NC;
    const int t = threadIdx.x;
    if (t < M) {
        int b = t / NC, j = t - b*NC;
        int tok = g_inp[b*SSQ + p0 + j];
        if (tok < 0 || tok >= VSZ) tok = 0;
        S.rpE [t] = P.emb + (long long)tok * DM;
        S.rpH [t] = g_h  + t*DM;
        S.rpH2[t] = g_h2 + t*DM;
        S.rpAO[t] = g_ao + t*DM;
        S.rpF1[t] = g_f1 + t*FFH;
    }
    if (t < 4) S.rpLM[t] = g_h + ((t+1)*NC - 1)*DM;
    if ((t & 31) < 16) S.sk[(t>>5)*4] = 0ull;  // harmless
    __syncthreads();

    // block 0 materializes g_h = embeddings (residual input for LN1 of layer 0)
    if (blockIdx.x == 0) {
        for (int i = t; i < M*DM; i += NTHR) {
            int r = i / DM, d = i - r*DM;
            g_h[i] = __ldg(S.rpE[r] + d);
        }
    }

    for (int l = 0; l < NL; l++) {
        qkv_phase<NC>(P, l, p0, (l == 0) ? S.rpE : S.rpH);                    gsync(gen);
        attn_phase<NC>(l, p0);                                                gsync(gen);
        gemm_phase<M,false>(S.rpAO, P.Wo + (long long)l*DM*DM,
                            P.bo + l*DM, g_r1, DM, DM);                       gsync(gen);
        ln_phase<M>(g_h, g_r1, P.ln1s + l*DM, P.ln1b + l*DM, g_h2);           gsync(gen);
        gemm_phase<M,true >(S.rpH2, P.W1 + (long long)l*DM*FFH,
                            P.b1 + l*FFH, g_f1, DM, FFH);                     gsync(gen);
        gemm_phase<M,false>(S.rpF1, P.W2 + (long long)l*FFH*DM,
                            P.b2 + l*DM, g_r2, FFH, DM);                      gsync(gen);
        ln_phase<M>(g_h2, g_r2, P.ln2s + l*DM, P.ln2b + l*DM, g_h);           gsync(gen);
    }
    lm_phase(P, S.rpLM, S.sk);                                                gsync(gen);
    if (blockIdx.x == 0 && threadIdx.x == 0) {
        bool alleos = true;
        for (int b = 0; b < BB; b++) {
            int tok = (int)(0xFFFFFFFFu - (unsigned)(g_best[b] & 0xFFFFFFFFu));
            g_inp[b*SSQ + cl + 1] = tok;
            P.out[b*32 + cl] = (float)tok;
            if (tok != EOS_TOK) alleos = false;
            g_best[b] = 0ull;
        }
        if (alleos) g_stop = 1;
    }
    gsync(gen);
}

// ------------------------- persistent mega-kernel -------------------------
__global__ __launch_bounds__(NTHR, 1)
void mega_kernel(Params P) {
    __shared__ Shr S;
    __shared__ unsigned s_gen;
    if (threadIdx.x == 0) s_gen = atomicAdd(&g_bar_gen, 0u);
    __syncthreads();
    unsigned gen = s_gen;

    if (blockIdx.x == 0) {
        int t = threadIdx.x;
        if (t < BB*SSQ) g_inp[t] = 0;
        if (t < BB*32)  P.out[t] = 0.f;
        __syncthreads();
        if (t == 0) g_stop = 0;
        if (t < BB) { g_inp[t*SSQ] = 1; g_best[t] = 0ull; }
        if (t < 32) {
            int tok = P.words[t];
            g_inp[(t >> 3)*SSQ + 1 + (t & 7)] = tok;
            P.out[(t >> 3)*32 + (t & 7)] = (float)tok;
        }
    }
    gsync(gen);

    // prefill: positions 0..8, token for cl=8
    do_step<9>(0, 8, P, gen, S);
    // decode
    for (int p = 9; p <= 31; p++) {
        if (*(volatile int*)&g_stop) break;   // uniform post-barrier
        do_step<1>(p, p, P, gen, S);
    }
}

// ------------------------- host -------------------------
extern "C" void kernel_launch(void* const* d_in, const int* in_sizes, int n_in,
                              void* d_out, int out_size) {
    (void)in_sizes; (void)out_size;
    int base = n_in - 19;
    Params P;
    P.words = (const int*)d_in[0];
    P.emb  = (const float*)d_in[base + 0];
    P.Wq   = (const float*)d_in[base + 1];
    P.bq   = (const float*)d_in[base + 2];
    P.Wk   = (const float*)d_in[base + 3];
    P.bk   = (const float*)d_in[base + 4];
    P.Wv   = (const float*)d_in[base + 5];
    P.bv   = (const float*)d_in[base + 6];
    P.Wo   = (const float*)d_in[base + 7];
    P.bo   = (const float*)d_in[base + 8];
    P.ln1s = (const float*)d_in[base + 9];
    P.ln1b = (const float*)d_in[base + 10];
    P.W1   = (const float*)d_in[base + 11];
    P.b1   = (const float*)d_in[base + 12];
    P.W2   = (const float*)d_in[base + 13];
    P.b2   = (const float*)d_in[base + 14];
    P.ln2s = (const float*)d_in[base + 15];
    P.ln2b = (const float*)d_in[base + 16];
    P.lmW  = (const float*)d_in[base + 17];
    P.lmb  = (const float*)d_in[base + 18];
    P.out  = (float*)d_out;

    mega_kernel<<<NBLK, NTHR>>>(P);
}

// round 14
// speedup vs baseline: 3.1594x; 3.1594x over previous
#include <cuda_runtime.h>
#include <math.h>

#define VSZ 30000
#define DM  640
#define NL  6
#define NH  8
#define DHD 80
#define FFH 2560
#define BB  4
#define SSQ 33
#define EOS_TOK 2
#define NBLK 148
#define NTHR 512
#define NWP  16              // warps per block
#define TOTW (NBLK*NWP)

struct Params {
    const int* words;
    const float *emb,*Wq,*bq,*Wk,*bk,*Wv,*bv,*Wo,*bo;
    const float *ln1s,*ln1b,*W1,*b1,*W2,*b2,*ln2s,*ln2b,*lmW,*lmb;
    float* out;
};

// ------------------------- device state -------------------------
__device__ unsigned g_bar_count;
__device__ unsigned g_bar_gen;
__device__ int g_stop;
__device__ int g_inp[BB*SSQ];
__device__ unsigned long long g_best[BB];
__device__ float g_h [36*DM];
__device__ float g_h2[36*DM];
__device__ float g_q [36*DM];
__device__ float g_ao[36*DM];
__device__ float g_r1[36*DM];
__device__ float g_f1[36*FFH];
__device__ float g_r2[36*DM];
__device__ float g_kc[NL*BB*SSQ*DM];
__device__ float g_vc[NL*BB*SSQ*DM];

struct Shr {
    const float* rpE[36];
    const float* rpH[36];
    const float* rpH2[36];
    const float* rpAO[36];
    const float* rpF1[36];
    const float* rpLM[4];
    unsigned long long swk[NWP];
    float s[16*NTHR];        // split-K reduction buffer (32KB)
};

// ------------------------- grid barrier (proven R12) -------------------------
__device__ __forceinline__ void gsync(unsigned &gen) {
    __syncthreads();
    if (threadIdx.x == 0) {
        __threadfence();
        unsigned arrived = atomicAdd(&g_bar_count, 1u);
        if (arrived == NBLK - 1u) {
            g_bar_count = 0u;
            __threadfence();
            atomicAdd(&g_bar_gen, 1u);
        } else {
            while (atomicAdd(&g_bar_gen, 0u) == gen) __nanosleep(32);
        }
        __threadfence();
    }
    gen++;
    __syncthreads();
}

// ------------------------- core 4-row x 128-col GEMM tile -------------------------
// block = 16 kslices (warp) x 32 colgroups (lane). Warp loads 512B contiguous W.
// acc[m][j] per thread; caller reduces via smem.
__device__ __forceinline__ void tile_dot(const float* const* rowp, int row0,
                                         const float* __restrict__ W, int N, int KL,
                                         int n4, bool valid, float acc[4][4]) {
#pragma unroll
    for (int m = 0; m < 4; m++)
#pragma unroll
        for (int j = 0; j < 4; j++) acc[m][j] = 0.f;
    if (!valid) return;
    const int ks = threadIdx.x >> 5;
    const float* a0 = rowp[row0+0] + ks*KL;
    const float* a1 = rowp[row0+1] + ks*KL;
    const float* a2 = rowp[row0+2] + ks*KL;
    const float* a3 = rowp[row0+3] + ks*KL;
    const char* Wb = (const char*)(W + (long long)(ks*KL)*N + n4);
    const long long step = (long long)N * 4;
#pragma unroll 8
    for (int kk = 0; kk < KL; kk++) {
        float4 w = __ldg((const float4*)(Wb + kk*step));
        float x0 = a0[kk], x1 = a1[kk], x2 = a2[kk], x3 = a3[kk];
        acc[0][0]=fmaf(x0,w.x,acc[0][0]); acc[0][1]=fmaf(x0,w.y,acc[0][1]);
        acc[0][2]=fmaf(x0,w.z,acc[0][2]); acc[0][3]=fmaf(x0,w.w,acc[0][3]);
        acc[1][0]=fmaf(x1,w.x,acc[1][0]); acc[1][1]=fmaf(x1,w.y,acc[1][1]);
        acc[1][2]=fmaf(x1,w.z,acc[1][2]); acc[1][3]=fmaf(x1,w.w,acc[1][3]);
        acc[2][0]=fmaf(x2,w.x,acc[2][0]); acc[2][1]=fmaf(x2,w.y,acc[2][1]);
        acc[2][2]=fmaf(x2,w.z,acc[2][2]); acc[2][3]=fmaf(x2,w.w,acc[2][3]);
        acc[3][0]=fmaf(x3,w.x,acc[3][0]); acc[3][1]=fmaf(x3,w.y,acc[3][1]);
        acc[3][2]=fmaf(x3,w.z,acc[3][2]); acc[3][3]=fmaf(x3,w.w,acc[3][3]);
    }
}

// stores acc to smem and reduces over 16 kslices; thread t owns (m=t>>7, col=t&127)
__device__ __forceinline__ float tile_reduce(float acc[4][4], float* s, int& m, int& col) {
    const int t = threadIdx.x;
    __syncthreads();
#pragma unroll
    for (int mm = 0; mm < 4; mm++)
#pragma unroll
        for (int j = 0; j < 4; j++) s[(mm*4+j)*NTHR + t] = acc[mm][j];
    __syncthreads();
    m = t >> 7; col = t & 127;
    int c2 = col >> 2, j = col & 3;
    float v = 0.f;
#pragma unroll
    for (int q = 0; q < 16; q++) v += s[(m*4+j)*NTHR + q*32 + c2];
    return v;
}

// ------------------------- generic GEMM phase -------------------------
template<int M, bool RELU>
__device__ void gemm_phase(const float* const* rowp, const float* __restrict__ W,
                           const float* __restrict__ bias, float* out,
                           int K, int N, float* s) {
    const int lane = threadIdx.x & 31;
    const int KL = K >> 4;
    const int nch = (N + 127) >> 7;
    for (int ch = blockIdx.x; ch < nch; ch += NBLK) {
        int n0 = ch << 7;
        int n4 = n0 + lane*4;
        bool valid = (n4 + 3 < N);
        for (int t0 = 0; t0 < M; t0 += 4) {
            float acc[4][4];
            tile_dot(rowp, t0, W, N, KL, n4, valid, acc);
            int m, col;
            float v = tile_reduce(acc, s, m, col);
            int n = n0 + col;
            if (n < N) {
                v += __ldg(bias + n);
                if (RELU) v = fmaxf(v, 0.f);
                out[(t0 + m)*N + n] = v;
            }
        }
    }
}

// ------------------------- QKV phase -------------------------
template<int NC>
__device__ void qkv_phase(const Params& P, int l, int p0,
                          const float* const* rowp, float* s) {
    constexpr int M = 4*NC;
    const int lane = threadIdx.x & 31;
    const int KL = DM >> 4;              // 40
    const int CPM = DM >> 7;             // 5 chunks of 128 per matrix
    for (int ch = blockIdx.x; ch < 3*CPM; ch += NBLK) {
        int sel = ch / CPM;
        int n0 = (ch - sel*CPM) << 7;
        int n4 = n0 + lane*4;
        const float* W    = ((sel==0) ? P.Wq : (sel==1) ? P.Wk : P.Wv) + (long long)l*DM*DM;
        const float* bias = ((sel==0) ? P.bq : (sel==1) ? P.bk : P.bv) + l*DM;
        for (int t0 = 0; t0 < M; t0 += 4) {
            float acc[4][4];
            tile_dot(rowp, t0, W, DM, KL, n4, true, acc);
            int m, col;
            float v = tile_reduce(acc, s, m, col);
            int n = n0 + col;
            v += __ldg(bias + n);
            int mg = t0 + m;
            int b = mg / NC, jj = mg - b*NC, p = p0 + jj;
            if (sel == 0)      g_q[mg*DM + n] = v;
            else if (sel == 1) g_kc[((l*BB + b)*SSQ + p)*DM + n] = v;
            else               g_vc[((l*BB + b)*SSQ + p)*DM + n] = v;
        }
    }
}

// ------------------------- LM head + argmax phase -------------------------
__device__ void lm_phase(const Params& P, const float* const* rowp,
                         float* s, unsigned long long* swk) {
    const int t = threadIdx.x;
    const int lane = t & 31, wp = t >> 5;
    const int KL = DM >> 4;              // 40
    const int nch = (VSZ + 127) >> 7;    // 235
    unsigned long long rb = 0ull;
    for (int ch = blockIdx.x; ch < nch; ch += NBLK) {
        int n0 = ch << 7;
        int n4 = n0 + lane*4;
        bool valid = (n4 + 3 < VSZ);
        float acc[4][4];
        tile_dot(rowp, 0, P.lmW, VSZ, KL, n4, valid, acc);
        int m, col;
        float v = tile_reduce(acc, s, m, col);
        int n = n0 + col;
        if (n < VSZ) {
            v += __ldg(P.lmb + n);
            unsigned u = __float_as_uint(v);
            u = (u & 0x80000000u) ? ~u : (u | 0x80000000u);
            unsigned long long key =
                ((unsigned long long)u << 32) | (unsigned)(0xFFFFFFFFu - (unsigned)n);
            if (key > rb) rb = key;       // this thread's b = t>>7 is fixed
        }
    }
    // warp max (warp spans one b: b = wp>>2)
#pragma unroll
    for (int o = 16; o > 0; o >>= 1) {
        unsigned long long u = __shfl_xor_sync(0xffffffffu, rb, o);
        if (u > rb) rb = u;
    }
    if (lane == 0) swk[wp] = rb;
    __syncthreads();
    if (t < 4) {
        unsigned long long bb = swk[t*4];
        for (int i = 1; i < 4; i++) if (swk[t*4 + i] > bb) bb = swk[t*4 + i];
        if (bb) atomicMax(&g_best[t], bb);
    }
}

// ------------------------- attention phase -------------------------
template<int NC>
__device__ void attn_phase(int l, int p0) {
    const int wp = threadIdx.x >> 5, lane = threadIdx.x & 31;
    const int total = BB*NH*NC;
    for (int tup = blockIdx.x*NWP + wp; tup < total; tup += TOTW) {
        int b = tup / (NH*NC);
        int rem = tup - b*NH*NC;
        int h = rem / NC, j = rem - h*NC;
        int p = p0 + j, nk = p + 1;
        int r = b*NC + j;
        float* qp = g_q + r*DM + h*DHD;
        float sc = -1e30f;
        if (lane < nk) {
            float* kp = g_kc + ((l*BB + b)*SSQ + lane)*DM + h*DHD;
            float sv = 0.f;
#pragma unroll
            for (int d = 0; d < DHD; d++) sv = fmaf(qp[d], kp[d], sv);
            sc = sv / sqrtf((float)DHD);
        }
        float mx = sc;
        for (int o = 16; o > 0; o >>= 1) mx = fmaxf(mx, __shfl_xor_sync(0xffffffffu, mx, o));
        float e = (lane < nk) ? expf(sc - mx) : 0.f;
        float sum = e;
        for (int o = 16; o > 0; o >>= 1) sum += __shfl_xor_sync(0xffffffffu, sum, o);
        float o0 = 0.f, o1 = 0.f, o2 = 0.f;
        float* vb = g_vc + ((l*BB + b)*SSQ)*DM + h*DHD;
        for (int jk = 0; jk < nk; jk++) {
            float pj = __shfl_sync(0xffffffffu, e, jk) / sum;
            float* vp = vb + jk*DM;
            o0 = fmaf(pj, vp[lane],      o0);
            o1 = fmaf(pj, vp[lane + 32], o1);
            if (lane < 16) o2 = fmaf(pj, vp[lane + 64], o2);
        }
        float* ao = g_ao + r*DM + h*DHD;
        ao[lane] = o0; ao[lane + 32] = o1;
        if (lane < 16) ao[lane + 64] = o2;
    }
}

// ------------------------- LayerNorm phase -------------------------
__device__ __forceinline__ void ln_row_warp(const float* a, const float* r,
                                            const float* __restrict__ sc,
                                            const float* __restrict__ bi,
                                            float* dst) {
    int lane = threadIdx.x & 31;
    float v[20];
    float sum = 0.f;
#pragma unroll
    for (int i = 0; i < 20; i++) {
        float x = a[lane + 32*i] + r[lane + 32*i];
        v[i] = x; sum += x;
    }
#pragma unroll
    for (int o = 16; o > 0; o >>= 1) sum += __shfl_xor_sync(0xffffffffu, sum, o);
    float mean = sum / DM;
    float vs = 0.f;
#pragma unroll
    for (int i = 0; i < 20; i++) { float d = v[i] - mean; vs += d*d; }
#pragma unroll
    for (int o = 16; o > 0; o >>= 1) vs += __shfl_xor_sync(0xffffffffu, vs, o);
    float dn = sqrtf(vs / DM + 1e-6f);
#pragma unroll
    for (int i = 0; i < 20; i++)
        dst[lane + 32*i] = (v[i] - mean) / dn * __ldg(sc + lane + 32*i)
                           + __ldg(bi + lane + 32*i);
}

template<int M>
__device__ void ln_phase(const float* a, const float* r,
                         const float* __restrict__ sc, const float* __restrict__ bi,
                         float* dst) {
    int gw = blockIdx.x*NWP + (threadIdx.x >> 5);
    for (int row = gw; row < M; row += TOTW)
        ln_row_warp(a + row*DM, r + row*DM, sc, bi, dst + row*DM);
}

// ------------------------- one generation step -------------------------
template<int NC>
__device__ void do_step(int p0, int cl, const Params& P, unsigned &gen, Shr& S) {
    constexpr int M = 4*NC;
    const int t = threadIdx.x;
    if (t < M) {
        int b = t / NC, j = t - b*NC;
        int tok = g_inp[b*SSQ + p0 + j];
        if (tok < 0 || tok >= VSZ) tok = 0;
        S.rpE [t] = P.emb + (long long)tok * DM;
        S.rpH [t] = g_h  + t*DM;
        S.rpH2[t] = g_h2 + t*DM;
        S.rpAO[t] = g_ao + t*DM;
        S.rpF1[t] = g_f1 + t*FFH;
    }
    if (t < 4) S.rpLM[t] = g_h + ((t+1)*NC - 1)*DM;
    __syncthreads();

    // block 0 materializes g_h = embeddings (residual for LN1 of layer 0)
    if (blockIdx.x == 0) {
        for (int i = t; i < M*DM; i += NTHR) {
            int r = i / DM, d = i - r*DM;
            g_h[i] = __ldg(S.rpE[r] + d);
        }
    }

    for (int l = 0; l < NL; l++) {
        qkv_phase<NC>(P, l, p0, (l == 0) ? S.rpE : S.rpH, S.s);               gsync(gen);
        attn_phase<NC>(l, p0);                                                gsync(gen);
        gemm_phase<M,false>(S.rpAO, P.Wo + (long long)l*DM*DM,
                            P.bo + l*DM, g_r1, DM, DM, S.s);                  gsync(gen);
        ln_phase<M>(g_h, g_r1, P.ln1s + l*DM, P.ln1b + l*DM, g_h2);           gsync(gen);
        gemm_phase<M,true >(S.rpH2, P.W1 + (long long)l*DM*FFH,
                            P.b1 + l*FFH, g_f1, DM, FFH, S.s);                gsync(gen);
        gemm_phase<M,false>(S.rpF1, P.W2 + (long long)l*FFH*DM,
                            P.b2 + l*DM, g_r2, FFH, DM, S.s);                 gsync(gen);
        ln_phase<M>(g_h2, g_r2, P.ln2s + l*DM, P.ln2b + l*DM, g_h);           gsync(gen);
    }
    lm_phase(P, S.rpLM, S.s, S.swk);                                          gsync(gen);
    if (blockIdx.x == 0 && threadIdx.x == 0) {
        bool alleos = true;
        for (int b = 0; b < BB; b++) {
            int tok = (int)(0xFFFFFFFFu - (unsigned)(g_best[b] & 0xFFFFFFFFu));
            g_inp[b*SSQ + cl + 1] = tok;
            P.out[b*32 + cl] = (float)tok;
            if (tok != EOS_TOK) alleos = false;
            g_best[b] = 0ull;
        }
        if (alleos) g_stop = 1;
    }
    gsync(gen);
}

// ------------------------- persistent mega-kernel -------------------------
__global__ __launch_bounds__(NTHR, 1)
void mega_kernel(Params P) {
    __shared__ Shr S;
    __shared__ unsigned s_gen;
    if (threadIdx.x == 0) s_gen = atomicAdd(&g_bar_gen, 0u);
    __syncthreads();
    unsigned gen = s_gen;

    if (blockIdx.x == 0) {
        int t = threadIdx.x;
        if (t < BB*SSQ) g_inp[t] = 0;
        if (t < BB*32)  P.out[t] = 0.f;
        __syncthreads();
        if (t == 0) g_stop = 0;
        if (t < BB) { g_inp[t*SSQ] = 1; g_best[t] = 0ull; }
        if (t < 32) {
            int tok = P.words[t];
            g_inp[(t >> 3)*SSQ + 1 + (t & 7)] = tok;
            P.out[(t >> 3)*32 + (t & 7)] = (float)tok;
        }
    }
    gsync(gen);

    do_step<9>(0, 8, P, gen, S);                 // prefill -> token at col 8
    for (int p = 9; p <= 31; p++) {
        if (*(volatile int*)&g_stop) break;      // uniform post-barrier
        do_step<1>(p, p, P, gen, S);
    }
}

// ------------------------- host -------------------------
extern "C" void kernel_launch(void* const* d_in, const int* in_sizes, int n_in,
                              void* d_out, int out_size) {
    (void)in_sizes; (void)out_size;
    int base = n_in - 19;
    Params P;
    P.words = (const int*)d_in[0];
    P.emb  = (const float*)d_in[base + 0];
    P.Wq   = (const float*)d_in[base + 1];
    P.bq   = (const float*)d_in[base + 2];
    P.Wk   = (const float*)d_in[base + 3];
    P.bk   = (const float*)d_in[base + 4];
    P.Wv   = (const float*)d_in[base + 5];
    P.bv   = (const float*)d_in[base + 6];
    P.Wo   = (const float*)d_in[base + 7];
    P.bo   = (const float*)d_in[base + 8];
    P.ln1s = (const float*)d_in[base + 9];
    P.ln1b = (const float*)d_in[base + 10];
    P.W1   = (const float*)d_in[base + 11];
    P.b1   = (const float*)d_in[base + 12];
    P.W2   = (const float*)d_in[base + 13];
    P.b2   = (const float*)d_in[base + 14];
    P.ln2s = (const float*)d_in[base + 15];
    P.ln2b = (const float*)d_in[base + 16];
    P.lmW  = (const float*)d_in[base + 17];
    P.lmb  = (const float*)d_in[base + 18];
    P.out  = (float*)d_out;

    mega_kernel<<<NBLK, NTHR>>>(P);
}

// round 15
// speedup vs baseline: 3.7613x; 1.1905x over previous
#include <cuda_runtime.h>
#include <math.h>

#define VSZ 30000
#define DM  640
#define NL  6
#define NH  8
#define DHD 80
#define FFH 2560
#define BB  4
#define SSQ 33
#define EOS_TOK 2
#define NBLK 96
#define NTHR 512
#define NWP  16
#define TOTW (NBLK*NWP)
#define KS   32              // k-slices per block
#define CW   64              // chunk width (columns)
#define CG   16              // float4 col-groups per chunk

struct Params {
    const int* words;
    const float *emb,*Wq,*bq,*Wk,*bk,*Wv,*bv,*Wo,*bo;
    const float *ln1s,*ln1b,*W1,*b1,*W2,*b2,*ln2s,*ln2b,*lmW,*lmb;
    float* out;
};

// ------------------------- device state -------------------------
__device__ unsigned g_bar_count;
__device__ unsigned g_bar_gen;
__device__ int g_stop;
__device__ int g_inp[BB*SSQ];
__device__ unsigned long long g_best[BB];
__device__ float g_h [36*DM];
__device__ float g_h2[36*DM];
__device__ float g_q [36*DM];
__device__ float g_ao[36*DM];
__device__ float g_r1[36*DM];
__device__ float g_f1[36*FFH];
__device__ float g_r2[36*DM];
__device__ float g_kc[NL*BB*SSQ*DM];
__device__ float g_vc[NL*BB*SSQ*DM];

struct Shr {
    const float* rpE[36];
    const float* rpH[36];
    const float* rpH2[36];
    const float* rpAO[36];
    const float* rpF1[36];
    const float* rpLM[4];
    unsigned long long sk[NTHR];
    float s[16*NTHR];        // split-K reduction buffer (32KB)
};

// ------------------------- grid barrier (proven) -------------------------
__device__ __forceinline__ void gsync(unsigned &gen) {
    __syncthreads();
    if (threadIdx.x == 0) {
        __threadfence();
        unsigned arrived = atomicAdd(&g_bar_count, 1u);
        if (arrived == NBLK - 1u) {
            g_bar_count = 0u;
            __threadfence();
            atomicAdd(&g_bar_gen, 1u);
        } else {
            while (atomicAdd(&g_bar_gen, 0u) == gen) __nanosleep(32);
        }
        __threadfence();
    }
    gen++;
    __syncthreads();
}

// ------------------------- 4-row x 64-col tile, 32-way split-K -------------------------
// thread t: cg = t&15 (float4 col group), ks = t>>4 (k-slice).
// warp = 16 cg x 2 ks -> two 256B contiguous rows. KL = K/32.
__device__ __forceinline__ void tile_dot(const float* const* rowp, int row0,
                                         const float* __restrict__ W, int N, int KL,
                                         int n0, bool valid, float acc[4][4]) {
#pragma unroll
    for (int m = 0; m < 4; m++)
#pragma unroll
        for (int j = 0; j < 4; j++) acc[m][j] = 0.f;
    if (!valid) return;
    const int cg = threadIdx.x & 15, ks = threadIdx.x >> 4;
    const float* a0 = rowp[row0+0] + ks*KL;
    const float* a1 = rowp[row0+1] + ks*KL;
    const float* a2 = rowp[row0+2] + ks*KL;
    const float* a3 = rowp[row0+3] + ks*KL;
    const char* Wb = (const char*)(W + (long long)(ks*KL)*N + n0 + cg*4);
    const long long step = (long long)N * 4;
#pragma unroll 8
    for (int kk = 0; kk < KL; kk++) {
        float4 w = __ldg((const float4*)(Wb + kk*step));
        float x0 = a0[kk], x1 = a1[kk], x2 = a2[kk], x3 = a3[kk];
        acc[0][0]=fmaf(x0,w.x,acc[0][0]); acc[0][1]=fmaf(x0,w.y,acc[0][1]);
        acc[0][2]=fmaf(x0,w.z,acc[0][2]); acc[0][3]=fmaf(x0,w.w,acc[0][3]);
        acc[1][0]=fmaf(x1,w.x,acc[1][0]); acc[1][1]=fmaf(x1,w.y,acc[1][1]);
        acc[1][2]=fmaf(x1,w.z,acc[1][2]); acc[1][3]=fmaf(x1,w.w,acc[1][3]);
        acc[2][0]=fmaf(x2,w.x,acc[2][0]); acc[2][1]=fmaf(x2,w.y,acc[2][1]);
        acc[2][2]=fmaf(x2,w.z,acc[2][2]); acc[2][3]=fmaf(x2,w.w,acc[2][3]);
        acc[3][0]=fmaf(x3,w.x,acc[3][0]); acc[3][1]=fmaf(x3,w.y,acc[3][1]);
        acc[3][2]=fmaf(x3,w.z,acc[3][2]); acc[3][3]=fmaf(x3,w.w,acc[3][3]);
    }
}

// reduce 32 k-slices via smem. threads t<256 own (m=t>>6, col=t&63); returns value.
__device__ __forceinline__ float tile_reduce(float acc[4][4], float* s, int& m, int& col) {
    const int t = threadIdx.x;
    __syncthreads();
#pragma unroll
    for (int mm = 0; mm < 4; mm++)
#pragma unroll
        for (int j = 0; j < 4; j++) s[(mm*4+j)*NTHR + t] = acc[mm][j];
    __syncthreads();
    if (t >= 256) { m = 0; col = -1; return 0.f; }
    m = t >> 6; col = t & 63;
    int cg2 = col >> 2, j = col & 3;
    float v = 0.f;
#pragma unroll
    for (int q = 0; q < KS; q++) v += s[(m*4+j)*NTHR + q*16 + cg2];
    return v;
}

// ------------------------- generic GEMM phase (N multiple of 64) -------------------------
template<int M, bool RELU>
__device__ void gemm_phase(const float* const* rowp, const float* __restrict__ W,
                           const float* __restrict__ bias, float* out,
                           int K, int N, float* s) {
    const int KL = K / KS;
    const int nch = N / CW;
    for (int ch = blockIdx.x; ch < nch; ch += NBLK) {
        int n0 = ch * CW;
        for (int t0 = 0; t0 < M; t0 += 4) {
            float acc[4][4];
            tile_dot(rowp, t0, W, N, KL, n0, true, acc);
            int m, col;
            float v = tile_reduce(acc, s, m, col);
            if (col >= 0) {
                int n = n0 + col;
                v += __ldg(bias + n);
                if (RELU) v = fmaxf(v, 0.f);
                out[(t0 + m)*N + n] = v;
            }
        }
    }
}

// ------------------------- QKV phase -------------------------
template<int NC>
__device__ void qkv_phase(const Params& P, int l, int p0,
                          const float* const* rowp, float* s) {
    constexpr int M = 4*NC;
    const int KL = DM / KS;              // 20
    const int CPM = DM / CW;             // 10
    for (int ch = blockIdx.x; ch < 3*CPM; ch += NBLK) {
        int sel = ch / CPM;
        int n0 = (ch - sel*CPM) * CW;
        const float* W    = ((sel==0) ? P.Wq : (sel==1) ? P.Wk : P.Wv) + (long long)l*DM*DM;
        const float* bias = ((sel==0) ? P.bq : (sel==1) ? P.bk : P.bv) + l*DM;
        for (int t0 = 0; t0 < M; t0 += 4) {
            float acc[4][4];
            tile_dot(rowp, t0, W, DM, KL, n0, true, acc);
            int m, col;
            float v = tile_reduce(acc, s, m, col);
            if (col >= 0) {
                int n = n0 + col;
                v += __ldg(bias + n);
                int mg = t0 + m;
                int b = mg / NC, jj = mg - b*NC, p = p0 + jj;
                if (sel == 0)      g_q[mg*DM + n] = v;
                else if (sel == 1) g_kc[((l*BB + b)*SSQ + p)*DM + n] = v;
                else               g_vc[((l*BB + b)*SSQ + p)*DM + n] = v;
            }
        }
    }
}

// ------------------------- LM head + argmax phase -------------------------
__device__ void lm_phase(const Params& P, const float* const* rowp,
                         float* s, unsigned long long* sk) {
    const int t = threadIdx.x;
    const int KL = DM / KS;              // 20
    const int nch = (VSZ + CW - 1) / CW; // 469
    unsigned long long rb = 0ull;
    for (int ch = blockIdx.x; ch < nch; ch += NBLK) {
        int n0 = ch * CW;
        int n4 = n0 + (t & 15)*4;
        bool valid = (n4 + 3 < VSZ);
        float acc[4][4];
        tile_dot(rowp, 0, P.lmW, VSZ, KL, n0, valid, acc);
        int m, col;
        float v = tile_reduce(acc, s, m, col);
        if (col >= 0) {
            int n = n0 + col;
            if (n < VSZ) {
                v += __ldg(P.lmb + n);
                unsigned u = __float_as_uint(v);
                u = (u & 0x80000000u) ? ~u : (u | 0x80000000u);
                unsigned long long key =
                    ((unsigned long long)u << 32) | (unsigned)(0xFFFFFFFFu - (unsigned)n);
                if (key > rb) rb = key;      // thread's b = t>>6 fixed
            }
        }
    }
    sk[t] = rb;
    __syncthreads();
    if (t < 4) {                             // thread b scans its 64 owners
        unsigned long long bb = 0ull;
        for (int i = 0; i < 64; i++) {
            unsigned long long v = sk[t*64 + i];
            if (v > bb) bb = v;
        }
        if (bb) atomicMax(&g_best[t], bb);
    }
    __syncthreads();
}

// ------------------------- attention phase -------------------------
template<int NC>
__device__ void attn_phase(int l, int p0) {
    const int wp = threadIdx.x >> 5, lane = threadIdx.x & 31;
    const int total = BB*NH*NC;
    for (int tup = blockIdx.x*NWP + wp; tup < total; tup += TOTW) {
        int b = tup / (NH*NC);
        int rem = tup - b*NH*NC;
        int h = rem / NC, j = rem - h*NC;
        int p = p0 + j, nk = p + 1;
        int r = b*NC + j;
        float* qp = g_q + r*DM + h*DHD;
        float sc = -1e30f;
        if (lane < nk) {
            float* kp = g_kc + ((l*BB + b)*SSQ + lane)*DM + h*DHD;
            float sv = 0.f;
#pragma unroll
            for (int d = 0; d < DHD; d++) sv = fmaf(qp[d], kp[d], sv);
            sc = sv / sqrtf((float)DHD);
        }
        float mx = sc;
        for (int o = 16; o > 0; o >>= 1) mx = fmaxf(mx, __shfl_xor_sync(0xffffffffu, mx, o));
        float e = (lane < nk) ? expf(sc - mx) : 0.f;
        float sum = e;
        for (int o = 16; o > 0; o >>= 1) sum += __shfl_xor_sync(0xffffffffu, sum, o);
        float o0 = 0.f, o1 = 0.f, o2 = 0.f;
        float* vb = g_vc + ((l*BB + b)*SSQ)*DM + h*DHD;
        for (int jk = 0; jk < nk; jk++) {
            float pj = __shfl_sync(0xffffffffu, e, jk) / sum;
            float* vp = vb + jk*DM;
            o0 = fmaf(pj, vp[lane],      o0);
            o1 = fmaf(pj, vp[lane + 32], o1);
            if (lane < 16) o2 = fmaf(pj, vp[lane + 64], o2);
        }
        float* ao = g_ao + r*DM + h*DHD;
        ao[lane] = o0; ao[lane + 32] = o1;
        if (lane < 16) ao[lane + 64] = o2;
    }
}

// ------------------------- LayerNorm phase -------------------------
__device__ __forceinline__ void ln_row_warp(const float* a, const float* r,
                                            const float* __restrict__ sc,
                                            const float* __restrict__ bi,
                                            float* dst) {
    int lane = threadIdx.x & 31;
    float v[20];
    float sum = 0.f;
#pragma unroll
    for (int i = 0; i < 20; i++) {
        float x = a[lane + 32*i] + r[lane + 32*i];
        v[i] = x; sum += x;
    }
#pragma unroll
    for (int o = 16; o > 0; o >>= 1) sum += __shfl_xor_sync(0xffffffffu, sum, o);
    float mean = sum / DM;
    float vs = 0.f;
#pragma unroll
    for (int i = 0; i < 20; i++) { float d = v[i] - mean; vs += d*d; }
#pragma unroll
    for (int o = 16; o > 0; o >>= 1) vs += __shfl_xor_sync(0xffffffffu, vs, o);
    float dn = sqrtf(vs / DM + 1e-6f);
#pragma unroll
    for (int i = 0; i < 20; i++)
        dst[lane + 32*i] = (v[i] - mean) / dn * __ldg(sc + lane + 32*i)
                           + __ldg(bi + lane + 32*i);
}

template<int M>
__device__ void ln_phase(const float* a, const float* r,
                         const float* __restrict__ sc, const float* __restrict__ bi,
                         float* dst) {
    int gw = blockIdx.x*NWP + (threadIdx.x >> 5);
    for (int row = gw; row < M; row += TOTW)
        ln_row_warp(a + row*DM, r + row*DM, sc, bi, dst + row*DM);
}

// ------------------------- one generation step -------------------------
template<int NC>
__device__ void do_step(int p0, int cl, const Params& P, unsigned &gen, Shr& S) {
    constexpr int M = 4*NC;
    const int t = threadIdx.x;
    if (t < M) {
        int b = t / NC, j = t - b*NC;
        int tok = g_inp[b*SSQ + p0 + j];
        if (tok < 0 || tok >= VSZ) tok = 0;
        S.rpE [t] = P.emb + (long long)tok * DM;
        S.rpH [t] = g_h  + t*DM;
        S.rpH2[t] = g_h2 + t*DM;
        S.rpAO[t] = g_ao + t*DM;
        S.rpF1[t] = g_f1 + t*FFH;
    }
    if (t < 4) S.rpLM[t] = g_h + ((t+1)*NC - 1)*DM;
    __syncthreads();

    // materialize g_h = embeddings (residual for LN1 of layer 0), striped by block
    for (int r = blockIdx.x; r < M; r += NBLK)
        for (int d = t; d < DM; d += NTHR)
            g_h[r*DM + d] = __ldg(S.rpE[r] + d);

    for (int l = 0; l < NL; l++) {
        qkv_phase<NC>(P, l, p0, (l == 0) ? S.rpE : S.rpH, S.s);               gsync(gen);
        attn_phase<NC>(l, p0);                                                gsync(gen);
        gemm_phase<M,false>(S.rpAO, P.Wo + (long long)l*DM*DM,
                            P.bo + l*DM, g_r1, DM, DM, S.s);                  gsync(gen);
        ln_phase<M>(g_h, g_r1, P.ln1s + l*DM, P.ln1b + l*DM, g_h2);           gsync(gen);
        gemm_phase<M,true >(S.rpH2, P.W1 + (long long)l*DM*FFH,
                            P.b1 + l*FFH, g_f1, DM, FFH, S.s);                gsync(gen);
        gemm_phase<M,false>(S.rpF1, P.W2 + (long long)l*FFH*DM,
                            P.b2 + l*DM, g_r2, FFH, DM, S.s);                 gsync(gen);
        ln_phase<M>(g_h2, g_r2, P.ln2s + l*DM, P.ln2b + l*DM, g_h);           gsync(gen);
    }
    lm_phase(P, S.rpLM, S.s, S.sk);                                           gsync(gen);
    if (blockIdx.x == 0 && threadIdx.x == 0) {
        bool alleos = true;
        for (int b = 0; b < BB; b++) {
            int tok = (int)(0xFFFFFFFFu - (unsigned)(g_best[b] & 0xFFFFFFFFu));
            g_inp[b*SSQ + cl + 1] = tok;
            P.out[b*32 + cl] = (float)tok;
            if (tok != EOS_TOK) alleos = false;
            g_best[b] = 0ull;
        }
        if (alleos) g_stop = 1;
    }
    gsync(gen);
}

// ------------------------- persistent mega-kernel -------------------------
__global__ __launch_bounds__(NTHR, 1)
void mega_kernel(Params P) {
    __shared__ Shr S;
    __shared__ unsigned s_gen;
    if (threadIdx.x == 0) s_gen = atomicAdd(&g_bar_gen, 0u);
    __syncthreads();
    unsigned gen = s_gen;

    if (blockIdx.x == 0) {
        int t = threadIdx.x;
        if (t < BB*SSQ) g_inp[t] = 0;
        if (t < BB*32)  P.out[t] = 0.f;
        __syncthreads();
        if (t == 0) g_stop = 0;
        if (t < BB) { g_inp[t*SSQ] = 1; g_best[t] = 0ull; }
        if (t < 32) {
            int tok = P.words[t];
            g_inp[(t >> 3)*SSQ + 1 + (t & 7)] = tok;
            P.out[(t >> 3)*32 + (t & 7)] = (float)tok;
        }
    }
    gsync(gen);

    do_step<9>(0, 8, P, gen, S);                 // prefill -> token at col 8
    for (int p = 9; p <= 31; p++) {
        if (*(volatile int*)&g_stop) break;      // uniform post-barrier
        do_step<1>(p, p, P, gen, S);
    }
}

// ------------------------- host -------------------------
extern "C" void kernel_launch(void* const* d_in, const int* in_sizes, int n_in,
                              void* d_out, int out_size) {
    (void)in_sizes; (void)out_size;
    int base = n_in - 19;
    Params P;
    P.words = (const int*)d_in[0];
    P.emb  = (const float*)d_in[base + 0];
    P.Wq   = (const float*)d_in[base + 1];
    P.bq   = (const float*)d_in[base + 2];
    P.Wk   = (const float*)d_in[base + 3];
    P.bk   = (const float*)d_in[base + 4];
    P.Wv   = (const float*)d_in[base + 5];
    P.bv   = (const float*)d_in[base + 6];
    P.Wo   = (const float*)d_in[base + 7];
    P.bo   = (const float*)d_in[base + 8];
    P.ln1s = (const float*)d_in[base + 9];
    P.ln1b = (const float*)d_in[base + 10];
    P.W1   = (const float*)d_in[base + 11];
    P.b1   = (const float*)d_in[base + 12];
    P.W2   = (const float*)d_in[base + 13];
    P.b2   = (const float*)d_in[base + 14];
    P.ln2s = (const float*)d_in[base + 15];
    P.ln2b = (const float*)d_in[base + 16];
    P.lmW  = (const float*)d_in[base + 17];
    P.lmb  = (const float*)d_in[base + 18];
    P.out  = (float*)d_out;

    mega_kernel<<<NBLK, NTHR>>>(P);
}